// round 6
// baseline (speedup 1.0000x reference)
#include <cuda_runtime.h>
#include <cuda_bf16.h>
#include <stdint.h>

// Problem constants (fixed by the dataset)
#define NMAX 100000
#define EMAX 1600000
#define DIN  256
#define DOUT 128

// ---------------- scratch (static device allocations; no runtime alloc) ----
static __device__ int    d_deg[NMAX];
static __device__ float  d_dinv[NMAX];
static __device__ int    d_rowstart[NMAX];
static __device__ int    d_cursor[NMAX];
static __device__ int    d_csr[EMAX];
static __device__ float4 d_g4[(size_t)NMAX * DOUT / 4];   // 51.2 MB, 16B-aligned
static __device__ int    d_tmpscan[NMAX];
static __device__ int    d_bsum[512];
static __device__ int    d_bsumscan[512];
static __device__ int    d_is64;   // 1 if edge_index delivered as int64, 0 if int32

// ---------------- dtype probe (device-side; graph-capturable) --------------
__global__ void k_detect(const void* __restrict__ ei) {
    // Interpret first 256 8-byte words as int64 node indices. True int64 data
    // is always in [0, NMAX). Packed-int32 data gives lo + hi*2^32 >= 2^32
    // unless hi (a node index) happens to be 0 (p ~ 1e-5 per word).
    const long long* p = (const long long*)ei;
    int ok64 = 1;
    for (int i = 0; i < 256; i++) {
        long long v = p[i];
        if (v < 0 || v >= NMAX) { ok64 = 0; break; }
    }
    d_is64 = ok64;
}

__device__ __forceinline__ int load_idx(const void* __restrict__ ei,
                                        size_t pos) {
    if (d_is64) return (int)((const long long*)ei)[pos];
    return ((const int*)ei)[pos];
}

// ---------------- small kernels -------------------------------------------
__global__ void k_init(int n) {
    int i = blockIdx.x * blockDim.x + threadIdx.x;
    if (i < n) d_deg[i] = 0;
}

__global__ void k_degree(const void* __restrict__ ei, int e) {
    int i = blockIdx.x * blockDim.x + threadIdx.x;
    if (i < e) {
        int d = load_idx(ei, (size_t)e + i);   // dst row
        atomicAdd(&d_deg[d], 1);
    }
}

__global__ void k_dinv(int n) {
    int i = blockIdx.x * blockDim.x + threadIdx.x;
    if (i < n) d_dinv[i] = rsqrtf((float)(d_deg[i] + 1));  // +1 = self-loop
}

// Inclusive block scan of deg, 512 elems/block
__global__ void k_scan1(int n) {
    __shared__ int s[512];
    int t = threadIdx.x;
    int i = blockIdx.x * 512 + t;
    s[t] = (i < n) ? d_deg[i] : 0;
    __syncthreads();
    #pragma unroll
    for (int off = 1; off < 512; off <<= 1) {
        int add = (t >= off) ? s[t - off] : 0;
        __syncthreads();
        s[t] += add;
        __syncthreads();
    }
    if (i < n) d_tmpscan[i] = s[t];
    if (t == 511) d_bsum[blockIdx.x] = s[511];
}

// Single-block inclusive scan of the block sums (nb <= 256)
__global__ void k_scan2(int nb) {
    __shared__ int s[256];
    int t = threadIdx.x;
    s[t] = (t < nb) ? d_bsum[t] : 0;
    __syncthreads();
    #pragma unroll
    for (int off = 1; off < 256; off <<= 1) {
        int add = (t >= off) ? s[t - off] : 0;
        __syncthreads();
        s[t] += add;
        __syncthreads();
    }
    if (t < nb) d_bsumscan[t] = s[t];
}

__global__ void k_scan3(int n) {
    int i = blockIdx.x * blockDim.x + threadIdx.x;
    if (i < n) {
        int b = i >> 9;
        int base = b ? d_bsumscan[b - 1] : 0;
        int rs = base + d_tmpscan[i] - d_deg[i];  // exclusive
        d_rowstart[i] = rs;
        d_cursor[i] = rs;
    }
}

__global__ void k_fill(const void* __restrict__ ei, int e) {
    int i = blockIdx.x * blockDim.x + threadIdx.x;
    if (i < e) {
        int s = load_idx(ei, (size_t)i);            // src
        int d = load_idx(ei, (size_t)e + i);        // dst
        int p = atomicAdd(&d_cursor[d], 1);
        d_csr[p] = s;
    }
}

// ---------------- GEMM: g[r,:] = dinv[r] * (x[r,:] @ W) -------------------
// BM=64, BN=128, BK=32, 256 threads, 8x4 register tile per thread.
__global__ __launch_bounds__(256) void k_gemm(const float* __restrict__ x,
                                              const float* __restrict__ W,
                                              int n) {
    __shared__ __align__(16) float As[32][68];  // [k][row], 16B-aligned rows
    __shared__ __align__(16) float Bs[32][128]; // [k][col]

    const int tid = threadIdx.x;
    const int tx = tid & 31;        // col group: cols tx*4 .. tx*4+3
    const int ty = tid >> 5;        // row group: rows ty*8 .. ty*8+7
    const int row0 = blockIdx.x * 64;

    float acc[8][4];
    #pragma unroll
    for (int i = 0; i < 8; i++)
        #pragma unroll
        for (int j = 0; j < 4; j++) acc[i][j] = 0.f;

    for (int kt = 0; kt < DIN; kt += 32) {
        // load A tile (64 rows x 32 k), transposed into As[k][row]
        #pragma unroll
        for (int j = 0; j < 2; j++) {
            int idx = tid + j * 256;         // 0..511 float4 slots
            int r = idx >> 3;
            int kk = (idx & 7) * 4;
            float4 v = make_float4(0.f, 0.f, 0.f, 0.f);
            int grow = row0 + r;
            if (grow < n)
                v = *(const float4*)(x + (size_t)grow * DIN + kt + kk);
            As[kk + 0][r] = v.x;
            As[kk + 1][r] = v.y;
            As[kk + 2][r] = v.z;
            As[kk + 3][r] = v.w;
        }
        // load B tile (32 k x 128 cols)
        #pragma unroll
        for (int j = 0; j < 4; j++) {
            int idx = tid + j * 256;         // 0..1023 float4 slots
            int kr = idx >> 5;
            int c = (idx & 31) * 4;
            *(float4*)&Bs[kr][c] = *(const float4*)(W + (size_t)(kt + kr) * DOUT + c);
        }
        __syncthreads();

        #pragma unroll
        for (int k = 0; k < 32; k++) {
            float4 a0 = *(const float4*)&As[k][ty * 8];     // in-warp broadcast
            float4 a1 = *(const float4*)&As[k][ty * 8 + 4];
            float4 bf = *(const float4*)&Bs[k][tx * 4];
            float av[8] = {a0.x, a0.y, a0.z, a0.w, a1.x, a1.y, a1.z, a1.w};
            float bv[4] = {bf.x, bf.y, bf.z, bf.w};
            #pragma unroll
            for (int i = 0; i < 8; i++)
                #pragma unroll
                for (int j = 0; j < 4; j++)
                    acc[i][j] += av[i] * bv[j];
        }
        __syncthreads();
    }

    #pragma unroll
    for (int i = 0; i < 8; i++) {
        int r = row0 + ty * 8 + i;
        if (r < n) {
            float dv = d_dinv[r];
            float4 o = make_float4(acc[i][0] * dv, acc[i][1] * dv,
                                   acc[i][2] * dv, acc[i][3] * dv);
            d_g4[(size_t)r * 32 + tx] = o;
        }
    }
}

// ---------------- Aggregate: out[d] = relu(dinv[d]*(g[d] + sum g[src]) + b)
// One warp per node; lane owns float4 column group `lane`.
__global__ __launch_bounds__(256) void k_agg(const float* __restrict__ bias,
                                             float* __restrict__ out, int n) {
    int gwarp = (blockIdx.x * blockDim.x + threadIdx.x) >> 5;
    int lane = threadIdx.x & 31;
    if (gwarp >= n) return;

    float4 acc = d_g4[(size_t)gwarp * 32 + lane];   // self-loop term

    int start = d_rowstart[gwarp];
    int cnt = d_deg[gwarp];
    int e = start, end = start + cnt;

    for (; e + 4 <= end; e += 4) {
        int s0 = d_csr[e + 0];
        int s1 = d_csr[e + 1];
        int s2 = d_csr[e + 2];
        int s3 = d_csr[e + 3];
        float4 v0 = d_g4[(size_t)s0 * 32 + lane];
        float4 v1 = d_g4[(size_t)s1 * 32 + lane];
        float4 v2 = d_g4[(size_t)s2 * 32 + lane];
        float4 v3 = d_g4[(size_t)s3 * 32 + lane];
        acc.x += (v0.x + v1.x) + (v2.x + v3.x);
        acc.y += (v0.y + v1.y) + (v2.y + v3.y);
        acc.z += (v0.z + v1.z) + (v2.z + v3.z);
        acc.w += (v0.w + v1.w) + (v2.w + v3.w);
    }
    for (; e < end; e++) {
        int s = d_csr[e];
        float4 v = d_g4[(size_t)s * 32 + lane];
        acc.x += v.x; acc.y += v.y; acc.z += v.z; acc.w += v.w;
    }

    float dv = d_dinv[gwarp];
    float4 bv = ((const float4*)bias)[lane];
    float4 o;
    o.x = fmaxf(fmaf(dv, acc.x, bv.x), 0.f);
    o.y = fmaxf(fmaf(dv, acc.y, bv.y), 0.f);
    o.z = fmaxf(fmaf(dv, acc.z, bv.z), 0.f);
    o.w = fmaxf(fmaf(dv, acc.w, bv.w), 0.f);
    ((float4*)out)[(size_t)gwarp * 32 + lane] = o;
}

// ---------------- launch ---------------------------------------------------
extern "C" void kernel_launch(void* const* d_in, const int* in_sizes, int n_in,
                              void* d_out, int out_size) {
    const float* x = (const float*)d_in[0];
    const void*  ei = (const void*)d_in[1];
    const float* W = (const float*)d_in[2];
    const float* bias = (const float*)d_in[3];
    float* out = (float*)d_out;

    int n = in_sizes[0] / DIN;    // 100000
    int e = in_sizes[1] / 2;      // 1600000 (element count is 2*E either dtype)
    int nb1 = (n + 511) / 512;    // 196 block sums (<= 256)

    k_detect<<<1, 1>>>(ei);
    k_init<<<(n + 255) / 256, 256>>>(n);
    k_degree<<<(e + 255) / 256, 256>>>(ei, e);
    k_dinv<<<(n + 255) / 256, 256>>>(n);
    k_scan1<<<nb1, 512>>>(n);
    k_scan2<<<1, 256>>>(nb1);
    k_scan3<<<(n + 255) / 256, 256>>>(n);
    k_fill<<<(e + 255) / 256, 256>>>(ei, e);
    k_gemm<<<(n + 63) / 64, 256>>>(x, W, n);
    k_agg<<<(n + 7) / 8, 256>>>(bias, out, n);
}